// round 14
// baseline (speedup 1.0000x reference)
#include <cuda_runtime.h>
#include <cuda_fp16.h>

#define NUM_USERS 100000
#define NUM_ITEMS 50000
#define NN        150000
#define EMBD      64
#define NNZ_C     4800000
#define CAP       96        // row bucket capacity, divisible by 8; P(deg>96) ~ 1e-26

// ---- scratch: __device__ globals (no allocation allowed) ----
__device__ int     g_cnt[NN];               // per-row cursor -> padded degree
__device__ int4    g_pair4[NN * CAP / 2];   // packed {col<<7, val_bits} pairs, 16B aligned
__device__ __half2 g_hh0[NN * 32];          // ego (fp16)
__device__ __half2 g_hh1[NN * 32];          // h1
__device__ __half2 g_hh2[NN * 32];          // h2

// ---- 1. zero cursors ----
__global__ void k_zero() {
    int i = blockIdx.x * blockDim.x + threadIdx.x;
    if (i < NN) g_cnt[i] = 0;
}

// ---- 2. scatter COO -> fixed-capacity row buckets (8 elems/thread, MLP=8) ----
// cols stored pre-scaled to byte offsets (col * 128)
__global__ void k_scatter(const int4* __restrict__ rows4,
                          const int4* __restrict__ cols4,
                          const float4* __restrict__ vals4) {
    int i = blockIdx.x * blockDim.x + threadIdx.x;
    if (i >= NNZ_C / 8) return;
    int2* pair = (int2*)g_pair4;
    int4   r0 = rows4[2 * i], r1 = rows4[2 * i + 1];
    int4   c0 = cols4[2 * i], c1 = cols4[2 * i + 1];
    float4 v0 = vals4[2 * i], v1 = vals4[2 * i + 1];
    int p0 = atomicAdd(&g_cnt[r0.x], 1);
    int p1 = atomicAdd(&g_cnt[r0.y], 1);
    int p2 = atomicAdd(&g_cnt[r0.z], 1);
    int p3 = atomicAdd(&g_cnt[r0.w], 1);
    int p4 = atomicAdd(&g_cnt[r1.x], 1);
    int p5 = atomicAdd(&g_cnt[r1.y], 1);
    int p6 = atomicAdd(&g_cnt[r1.z], 1);
    int p7 = atomicAdd(&g_cnt[r1.w], 1);
    if (p0 < CAP) pair[r0.x * CAP + p0] = make_int2(c0.x << 7, __float_as_int(v0.x));
    if (p1 < CAP) pair[r0.y * CAP + p1] = make_int2(c0.y << 7, __float_as_int(v0.y));
    if (p2 < CAP) pair[r0.z * CAP + p2] = make_int2(c0.z << 7, __float_as_int(v0.z));
    if (p3 < CAP) pair[r0.w * CAP + p3] = make_int2(c0.w << 7, __float_as_int(v0.w));
    if (p4 < CAP) pair[r1.x * CAP + p4] = make_int2(c1.x << 7, __float_as_int(v1.x));
    if (p5 < CAP) pair[r1.y * CAP + p5] = make_int2(c1.y << 7, __float_as_int(v1.y));
    if (p6 < CAP) pair[r1.z * CAP + p6] = make_int2(c1.z << 7, __float_as_int(v1.z));
    if (p7 < CAP) pair[r1.w * CAP + p7] = make_int2(c1.w << 7, __float_as_int(v1.w));
}

// ---- 3. pad each row bucket to a multiple of 8 with {col=0, val=0} dummies ----
// (makes the SpMM inner loop branch-free / fully chunked)
__global__ void k_pad() {
    int w = blockIdx.x * blockDim.x + threadIdx.x;
    if (w >= NN) return;
    int deg = g_cnt[w];
    if (deg > CAP) deg = CAP;
    int deg8 = (deg + 7) & ~7;
    int2* row = (int2*)g_pair4 + w * CAP;
    for (int j = deg; j < deg8; j++) row[j] = make_int2(0, 0);
    g_cnt[w] = deg8;
}

// ---- 4. init: out = ego (fp32), hh0 = ego (fp16) ----
__global__ void k_init(const float4* __restrict__ eu,
                       const float4* __restrict__ ei,
                       float4* __restrict__ out) {
    int i = blockIdx.x * blockDim.x + threadIdx.x;
    const int NU4 = NUM_USERS * EMBD / 4;
    const int NT4 = NN * EMBD / 4;
    if (i >= NT4) return;
    float4 v = (i < NU4) ? eu[i] : ei[i - NU4];
    out[i] = v;
    g_hh0[2 * i + 0] = __floats2half2_rn(v.x, v.y);
    g_hh0[2 * i + 1] = __floats2half2_rn(v.z, v.w);
}

// ---- 5-7. SpMM: warp-per-row, fp16 gather, fp32 acc, software-pipelined pairs ----
// LAYER 0: hh0 -> hh1 ; LAYER 1: hh1 -> hh2 ;
// LAYER 2: gather hh2 -> regs, fused out = (ego + h1 + h2 + h3) * 0.25
template <int LAYER>
__global__ void __launch_bounds__(256) k_spmm(float2* __restrict__ o2) {
    int w = (blockIdx.x * blockDim.x + threadIdx.x) >> 5;
    if (w >= NN) return;
    int lane = threadIdx.x & 31;

    const char* src = (const char*)((LAYER == 0) ? g_hh0 :
                                    (LAYER == 1) ? g_hh1 : g_hh2)
                    + lane * 4;
    const int4* __restrict__ pb = g_pair4 + w * (CAP / 2);

    int deg8 = g_cnt[w];       // padded degree, multiple of 8
    int nch  = deg8 >> 3;      // 8-nnz chunks

    float ax = 0.f, ay = 0.f;
    int4 A0, A1, A2, A3;       // current chunk: 8 packed pairs
    if (nch > 0) {
        A0 = pb[0]; A1 = pb[1]; A2 = pb[2]; A3 = pb[3];
    }
    for (int c = 0; c < nch; c++) {
        // 8 independent gathers for the current chunk (cols are byte offsets)
        __half2 x0 = *(const __half2*)(src + A0.x);
        __half2 x1 = *(const __half2*)(src + A0.z);
        __half2 x2 = *(const __half2*)(src + A1.x);
        __half2 x3 = *(const __half2*)(src + A1.z);
        __half2 x4 = *(const __half2*)(src + A2.x);
        __half2 x5 = *(const __half2*)(src + A2.z);
        __half2 x6 = *(const __half2*)(src + A3.x);
        __half2 x7 = *(const __half2*)(src + A3.z);
        // prefetch next chunk's pairs while gathers are in flight
        int4 B0, B1, B2, B3;
        if (c + 1 < nch) {
            const int4* nb = pb + (c + 1) * 4;
            B0 = nb[0]; B1 = nb[1]; B2 = nb[2]; B3 = nb[3];
        }
        float2 f;
        float  v;
        f = __half22float2(x0); v = __int_as_float(A0.y); ax += v * f.x; ay += v * f.y;
        f = __half22float2(x1); v = __int_as_float(A0.w); ax += v * f.x; ay += v * f.y;
        f = __half22float2(x2); v = __int_as_float(A1.y); ax += v * f.x; ay += v * f.y;
        f = __half22float2(x3); v = __int_as_float(A1.w); ax += v * f.x; ay += v * f.y;
        f = __half22float2(x4); v = __int_as_float(A2.y); ax += v * f.x; ay += v * f.y;
        f = __half22float2(x5); v = __int_as_float(A2.w); ax += v * f.x; ay += v * f.y;
        f = __half22float2(x6); v = __int_as_float(A3.y); ax += v * f.x; ay += v * f.y;
        f = __half22float2(x7); v = __int_as_float(A3.w); ax += v * f.x; ay += v * f.y;
        A0 = B0; A1 = B1; A2 = B2; A3 = B3;
    }

    int oi = w * 32 + lane;
    if (LAYER == 0) {
        g_hh1[oi] = __floats2half2_rn(ax, ay);
    } else if (LAYER == 1) {
        g_hh2[oi] = __floats2half2_rn(ax, ay);
    } else {
        float2 o  = o2[oi];                       // ego (exact fp32)
        float2 h1 = __half22float2(g_hh1[oi]);
        float2 h2 = __half22float2(g_hh2[oi]);
        o.x = (o.x + h1.x + h2.x + ax) * 0.25f;
        o.y = (o.y + h1.y + h2.y + ay) * 0.25f;
        o2[oi] = o;
    }
}

extern "C" void kernel_launch(void* const* d_in, const int* in_sizes, int n_in,
                              void* d_out, int out_size) {
    const float* eu   = (const float*)d_in[0];   // emb_user  [100000*64]
    const float* ei   = (const float*)d_in[1];   // emb_item  [50000*64]
    const float* vals = (const float*)d_in[2];   // adj_vals  [NNZ]
    const int*   rows = (const int*)d_in[3];     // adj_rows  [NNZ]
    const int*   cols = (const int*)d_in[4];     // adj_cols  [NNZ]
    float* out = (float*)d_out;                  // [150000*64] f32

    k_zero<<<(NN + 255) / 256, 256>>>();
    k_scatter<<<(NNZ_C / 8 + 255) / 256, 256>>>(
        (const int4*)rows, (const int4*)cols, (const float4*)vals);
    k_pad<<<(NN + 255) / 256, 256>>>();
    k_init<<<(NN * EMBD / 4 + 255) / 256, 256>>>(
        (const float4*)eu, (const float4*)ei, (float4*)out);

    int sb = (NN * 32 + 255) / 256;  // warp per row
    k_spmm<0><<<sb, 256>>>((float2*)out);
    k_spmm<1><<<sb, 256>>>((float2*)out);
    k_spmm<2><<<sb, 256>>>((float2*)out);
}

// round 15
// speedup vs baseline: 1.2807x; 1.2807x over previous
#include <cuda_runtime.h>
#include <cuda_fp16.h>

#define NUM_USERS 100000
#define NUM_ITEMS 50000
#define NN        150000
#define EMBD      64
#define NNZ_C     4800000
#define CAP       96        // row bucket capacity; P(Poisson(32) > 96) ~ 1e-26

// ---- scratch: __device__ globals (no allocation allowed) ----
__device__ int     g_cnt[NN];               // per-row cursor / degree
__device__ int2    g_pair[NN * CAP];        // packed {col<<7, val_bits}, row-bucketed
__device__ __half2 g_hh0[NN * 32];          // ego (fp16)
__device__ __half2 g_hh1[NN * 32];          // h1
__device__ __half2 g_hh2[NN * 32];          // h2

// ---- 1. zero cursors ----
__global__ void k_zero() {
    int i = blockIdx.x * blockDim.x + threadIdx.x;
    if (i < NN) g_cnt[i] = 0;
}

// ---- 2. scatter COO -> fixed-capacity row buckets (8 elems/thread, MLP=8) ----
// cols stored pre-scaled to byte offsets (col * 128)
__global__ void k_scatter(const int4* __restrict__ rows4,
                          const int4* __restrict__ cols4,
                          const float4* __restrict__ vals4) {
    int i = blockIdx.x * blockDim.x + threadIdx.x;
    if (i >= NNZ_C / 8) return;
    int4   r0 = rows4[2 * i], r1 = rows4[2 * i + 1];
    int4   c0 = cols4[2 * i], c1 = cols4[2 * i + 1];
    float4 v0 = vals4[2 * i], v1 = vals4[2 * i + 1];
    int p0 = atomicAdd(&g_cnt[r0.x], 1);
    int p1 = atomicAdd(&g_cnt[r0.y], 1);
    int p2 = atomicAdd(&g_cnt[r0.z], 1);
    int p3 = atomicAdd(&g_cnt[r0.w], 1);
    int p4 = atomicAdd(&g_cnt[r1.x], 1);
    int p5 = atomicAdd(&g_cnt[r1.y], 1);
    int p6 = atomicAdd(&g_cnt[r1.z], 1);
    int p7 = atomicAdd(&g_cnt[r1.w], 1);
    if (p0 < CAP) g_pair[r0.x * CAP + p0] = make_int2(c0.x << 7, __float_as_int(v0.x));
    if (p1 < CAP) g_pair[r0.y * CAP + p1] = make_int2(c0.y << 7, __float_as_int(v0.y));
    if (p2 < CAP) g_pair[r0.z * CAP + p2] = make_int2(c0.z << 7, __float_as_int(v0.z));
    if (p3 < CAP) g_pair[r0.w * CAP + p3] = make_int2(c0.w << 7, __float_as_int(v0.w));
    if (p4 < CAP) g_pair[r1.x * CAP + p4] = make_int2(c1.x << 7, __float_as_int(v1.x));
    if (p5 < CAP) g_pair[r1.y * CAP + p5] = make_int2(c1.y << 7, __float_as_int(v1.y));
    if (p6 < CAP) g_pair[r1.z * CAP + p6] = make_int2(c1.z << 7, __float_as_int(v1.z));
    if (p7 < CAP) g_pair[r1.w * CAP + p7] = make_int2(c1.w << 7, __float_as_int(v1.w));
}

// ---- 3. init: out = ego (fp32), hh0 = ego (fp16) ----
__global__ void k_init(const float4* __restrict__ eu,
                       const float4* __restrict__ ei,
                       float4* __restrict__ out) {
    int i = blockIdx.x * blockDim.x + threadIdx.x;
    const int NU4 = NUM_USERS * EMBD / 4;
    const int NT4 = NN * EMBD / 4;
    if (i >= NT4) return;
    float4 v = (i < NU4) ? eu[i] : ei[i - NU4];
    out[i] = v;
    g_hh0[2 * i + 0] = __floats2half2_rn(v.x, v.y);
    g_hh0[2 * i + 1] = __floats2half2_rn(v.z, v.w);
}

// ---- 4-6. SpMM: warp-per-row, fp16 gather, fp32 acc, straight-line 8-unroll ----
// LAYER 0: hh0 -> hh1 ; LAYER 1: hh1 -> hh2 ;
// LAYER 2: gather hh2 -> regs, fused out = (ego + h1 + h2 + h3) * 0.25
template <int LAYER>
__global__ void __launch_bounds__(256) k_spmm(float2* __restrict__ o2) {
    int w = (blockIdx.x * blockDim.x + threadIdx.x) >> 5;
    if (w >= NN) return;
    int lane = threadIdx.x & 31;

    const char* src = (const char*)((LAYER == 0) ? g_hh0 :
                                    (LAYER == 1) ? g_hh1 : g_hh2)
                    + lane * 4;

    int beg = w * CAP;
    int deg = g_cnt[w];
    if (deg > CAP) deg = CAP;
    int end = beg + deg;

    float ax = 0.f, ay = 0.f;
    int j = beg;
    // 8 nnz per iter: 4 int4 pair loads + 8 independent gathers, straight-line
    for (; j + 8 <= end; j += 8) {
        const int4* q = (const int4*)(g_pair + j);  // 16B-aligned (row base 768B)
        int4 q0 = q[0], q1 = q[1], q2 = q[2], q3 = q[3];
        __half2 x0 = *(const __half2*)(src + q0.x);
        __half2 x1 = *(const __half2*)(src + q0.z);
        __half2 x2 = *(const __half2*)(src + q1.x);
        __half2 x3 = *(const __half2*)(src + q1.z);
        __half2 x4 = *(const __half2*)(src + q2.x);
        __half2 x5 = *(const __half2*)(src + q2.z);
        __half2 x6 = *(const __half2*)(src + q3.x);
        __half2 x7 = *(const __half2*)(src + q3.z);
        float2 f;
        float  v;
        f = __half22float2(x0); v = __int_as_float(q0.y); ax += v * f.x; ay += v * f.y;
        f = __half22float2(x1); v = __int_as_float(q0.w); ax += v * f.x; ay += v * f.y;
        f = __half22float2(x2); v = __int_as_float(q1.y); ax += v * f.x; ay += v * f.y;
        f = __half22float2(x3); v = __int_as_float(q1.w); ax += v * f.x; ay += v * f.y;
        f = __half22float2(x4); v = __int_as_float(q2.y); ax += v * f.x; ay += v * f.y;
        f = __half22float2(x5); v = __int_as_float(q2.w); ax += v * f.x; ay += v * f.y;
        f = __half22float2(x6); v = __int_as_float(q3.y); ax += v * f.x; ay += v * f.y;
        f = __half22float2(x7); v = __int_as_float(q3.w); ax += v * f.x; ay += v * f.y;
    }
    for (; j < end; j++) {
        int2 p = g_pair[j];
        float2 f = __half22float2(*(const __half2*)(src + p.x));
        float v = __int_as_float(p.y);
        ax += v * f.x; ay += v * f.y;
    }

    int oi = w * 32 + lane;
    if (LAYER == 0) {
        g_hh1[oi] = __floats2half2_rn(ax, ay);
    } else if (LAYER == 1) {
        g_hh2[oi] = __floats2half2_rn(ax, ay);
    } else {
        float2 o  = o2[oi];                       // ego (exact fp32)
        float2 h1 = __half22float2(g_hh1[oi]);
        float2 h2 = __half22float2(g_hh2[oi]);
        o.x = (o.x + h1.x + h2.x + ax) * 0.25f;
        o.y = (o.y + h1.y + h2.y + ay) * 0.25f;
        o2[oi] = o;
    }
}

extern "C" void kernel_launch(void* const* d_in, const int* in_sizes, int n_in,
                              void* d_out, int out_size) {
    const float* eu   = (const float*)d_in[0];   // emb_user  [100000*64]
    const float* ei   = (const float*)d_in[1];   // emb_item  [50000*64]
    const float* vals = (const float*)d_in[2];   // adj_vals  [NNZ]
    const int*   rows = (const int*)d_in[3];     // adj_rows  [NNZ]
    const int*   cols = (const int*)d_in[4];     // adj_cols  [NNZ]
    float* out = (float*)d_out;                  // [150000*64] f32

    k_zero<<<(NN + 255) / 256, 256>>>();
    k_scatter<<<(NNZ_C / 8 + 255) / 256, 256>>>(
        (const int4*)rows, (const int4*)cols, (const float4*)vals);
    k_init<<<(NN * EMBD / 4 + 255) / 256, 256>>>(
        (const float4*)eu, (const float4*)ei, (float4*)out);

    int sb = (NN * 32 + 255) / 256;  // warp per row
    k_spmm<0><<<sb, 256>>>((float2*)out);
    k_spmm<1><<<sb, 256>>>((float2*)out);
    k_spmm<2><<<sb, 256>>>((float2*)out);
}

// round 16
// speedup vs baseline: 1.2879x; 1.0057x over previous
#include <cuda_runtime.h>
#include <cuda_fp16.h>

#define NUM_USERS 100000
#define NUM_ITEMS 50000
#define NN        150000
#define EMBD      64
#define NNZ_C     4800000
#define CAP       96        // row bucket capacity; P(Poisson(32) > 96) ~ 1e-26

// ---- scratch: __device__ globals (no allocation allowed) ----
__device__ int     g_cnt[NN];               // per-row cursor / degree
__device__ int2    g_pair[NN * CAP];        // packed {col*32, val as dup half2}
__device__ __half2 g_hh0[NN * 32];          // ego (fp16)
__device__ __half2 g_hh1[NN * 32];          // h1
__device__ __half2 g_hh2[NN * 32];          // h2

// ---- 1. init: g_cnt = 0, out = ego (fp32), hh0 = ego (fp16) ----
__global__ void k_init(const float4* __restrict__ eu,
                       const float4* __restrict__ ei,
                       float4* __restrict__ out) {
    int i = blockIdx.x * blockDim.x + threadIdx.x;
    if (i < NN) g_cnt[i] = 0;
    const int NU4 = NUM_USERS * EMBD / 4;
    const int NT4 = NN * EMBD / 4;
    if (i >= NT4) return;
    float4 v = (i < NU4) ? eu[i] : ei[i - NU4];
    out[i] = v;
    g_hh0[2 * i + 0] = __floats2half2_rn(v.x, v.y);
    g_hh0[2 * i + 1] = __floats2half2_rn(v.z, v.w);
}

// ---- 2. scatter COO -> fixed-capacity row buckets (8 elems/thread, MLP=8) ----
// pair = {col*32 (half2-index of row base), val duplicated into half2}
__device__ __forceinline__ int pack_val_h2(float v) {
    unsigned short hb = __half_as_ushort(__float2half_rn(v));
    return (int)(((unsigned)hb << 16) | (unsigned)hb);
}

__global__ void k_scatter(const int4* __restrict__ rows4,
                          const int4* __restrict__ cols4,
                          const float4* __restrict__ vals4) {
    int i = blockIdx.x * blockDim.x + threadIdx.x;
    if (i >= NNZ_C / 8) return;
    int4   r0 = rows4[2 * i], r1 = rows4[2 * i + 1];
    int4   c0 = cols4[2 * i], c1 = cols4[2 * i + 1];
    float4 v0 = vals4[2 * i], v1 = vals4[2 * i + 1];
    int p0 = atomicAdd(&g_cnt[r0.x], 1);
    int p1 = atomicAdd(&g_cnt[r0.y], 1);
    int p2 = atomicAdd(&g_cnt[r0.z], 1);
    int p3 = atomicAdd(&g_cnt[r0.w], 1);
    int p4 = atomicAdd(&g_cnt[r1.x], 1);
    int p5 = atomicAdd(&g_cnt[r1.y], 1);
    int p6 = atomicAdd(&g_cnt[r1.z], 1);
    int p7 = atomicAdd(&g_cnt[r1.w], 1);
    if (p0 < CAP) g_pair[r0.x * CAP + p0] = make_int2(c0.x * 32, pack_val_h2(v0.x));
    if (p1 < CAP) g_pair[r0.y * CAP + p1] = make_int2(c0.y * 32, pack_val_h2(v0.y));
    if (p2 < CAP) g_pair[r0.z * CAP + p2] = make_int2(c0.z * 32, pack_val_h2(v0.z));
    if (p3 < CAP) g_pair[r0.w * CAP + p3] = make_int2(c0.w * 32, pack_val_h2(v0.w));
    if (p4 < CAP) g_pair[r1.x * CAP + p4] = make_int2(c1.x * 32, pack_val_h2(v1.x));
    if (p5 < CAP) g_pair[r1.y * CAP + p5] = make_int2(c1.y * 32, pack_val_h2(v1.y));
    if (p6 < CAP) g_pair[r1.z * CAP + p6] = make_int2(c1.z * 32, pack_val_h2(v1.z));
    if (p7 < CAP) g_pair[r1.w * CAP + p7] = make_int2(c1.w * 32, pack_val_h2(v1.w));
}

// ---- 3-5. SpMM: warp-per-row, fp16 gather, HFMA2 chunk accumulate, fp32 total ----
// LAYER 0: hh0 -> hh1 ; LAYER 1: hh1 -> hh2 ;
// LAYER 2: gather hh2 -> regs, fused out = (ego + h1 + h2 + h3) * 0.25
template <int LAYER>
__global__ void __launch_bounds__(256) k_spmm(float2* __restrict__ o2) {
    int w = (blockIdx.x * blockDim.x + threadIdx.x) >> 5;
    if (w >= NN) return;
    int lane = threadIdx.x & 31;

    const __half2* __restrict__ src =
        (LAYER == 0) ? g_hh0 : (LAYER == 1) ? g_hh1 : g_hh2;

    int beg = w * CAP;
    int deg = g_cnt[w];
    if (deg > CAP) deg = CAP;
    int end = beg + deg;

    const __half2 hz = __float2half2_rn(0.f);
    float ax = 0.f, ay = 0.f;
    int j = beg;
    // 8 nnz per iter: 8 int2 pair loads + 8 independent gathers (R10 shape),
    // math = 1 HFMA2/nnz into two interleaved half2 accumulators (chain 4),
    // flushed to fp32 once per chunk.
    for (; j + 8 <= end; j += 8) {
        int2 p0 = g_pair[j + 0], p1 = g_pair[j + 1];
        int2 p2 = g_pair[j + 2], p3 = g_pair[j + 3];
        int2 p4 = g_pair[j + 4], p5 = g_pair[j + 5];
        int2 p6 = g_pair[j + 6], p7 = g_pair[j + 7];
        __half2 x0 = src[p0.x + lane];
        __half2 x1 = src[p1.x + lane];
        __half2 x2 = src[p2.x + lane];
        __half2 x3 = src[p3.x + lane];
        __half2 x4 = src[p4.x + lane];
        __half2 x5 = src[p5.x + lane];
        __half2 x6 = src[p6.x + lane];
        __half2 x7 = src[p7.x + lane];
        __half2 accA = hz, accB = hz;
        accA = __hfma2(*(const __half2*)&p0.y, x0, accA);
        accB = __hfma2(*(const __half2*)&p1.y, x1, accB);
        accA = __hfma2(*(const __half2*)&p2.y, x2, accA);
        accB = __hfma2(*(const __half2*)&p3.y, x3, accB);
        accA = __hfma2(*(const __half2*)&p4.y, x4, accA);
        accB = __hfma2(*(const __half2*)&p5.y, x5, accB);
        accA = __hfma2(*(const __half2*)&p6.y, x6, accA);
        accB = __hfma2(*(const __half2*)&p7.y, x7, accB);
        float2 fA = __half22float2(accA);
        float2 fB = __half22float2(accB);
        ax += fA.x + fB.x;
        ay += fA.y + fB.y;
    }
    // remainder (< 8 nnz): same HFMA2 path, single accumulator, one flush
    {
        __half2 accA = hz;
        for (; j < end; j++) {
            int2 p = g_pair[j];
            accA = __hfma2(*(const __half2*)&p.y, src[p.x + lane], accA);
        }
        float2 fA = __half22float2(accA);
        ax += fA.x;
        ay += fA.y;
    }

    int oi = w * 32 + lane;
    if (LAYER == 0) {
        g_hh1[oi] = __floats2half2_rn(ax, ay);
    } else if (LAYER == 1) {
        g_hh2[oi] = __floats2half2_rn(ax, ay);
    } else {
        float2 o  = o2[oi];                       // ego (exact fp32)
        float2 h1 = __half22float2(g_hh1[oi]);
        float2 h2 = __half22float2(g_hh2[oi]);
        o.x = (o.x + h1.x + h2.x + ax) * 0.25f;
        o.y = (o.y + h1.y + h2.y + ay) * 0.25f;
        o2[oi] = o;
    }
}

extern "C" void kernel_launch(void* const* d_in, const int* in_sizes, int n_in,
                              void* d_out, int out_size) {
    const float* eu   = (const float*)d_in[0];   // emb_user  [100000*64]
    const float* ei   = (const float*)d_in[1];   // emb_item  [50000*64]
    const float* vals = (const float*)d_in[2];   // adj_vals  [NNZ]
    const int*   rows = (const int*)d_in[3];     // adj_rows  [NNZ]
    const int*   cols = (const int*)d_in[4];     // adj_cols  [NNZ]
    float* out = (float*)d_out;                  // [150000*64] f32

    // init (also zeroes cursors) must precede scatter
    k_init<<<(NN * EMBD / 4 + 255) / 256, 256>>>(
        (const float4*)eu, (const float4*)ei, (float4*)out);
    k_scatter<<<(NNZ_C / 8 + 255) / 256, 256>>>(
        (const int4*)rows, (const int4*)cols, (const float4*)vals);

    int sb = (NN * 32 + 255) / 256;  // warp per row
    k_spmm<0><<<sb, 256>>>((float2*)out);
    k_spmm<1><<<sb, 256>>>((float2*)out);
    k_spmm<2><<<sb, 256>>>((float2*)out);
}

// round 17
// speedup vs baseline: 1.4000x; 1.0870x over previous
#include <cuda_runtime.h>
#include <cuda_fp16.h>

#define NUM_USERS 100000
#define NUM_ITEMS 50000
#define NN        150000
#define EMBD      64
#define NNZ_C     4800000
#define CAP       96        // row bucket capacity; P(Poisson(32) > 96) ~ 1e-26

// ---- scratch: __device__ globals (no allocation allowed) ----
__device__ int     g_cnt[NN];               // per-row cursor / degree
__device__ int2    g_pair[NN * CAP];        // packed {col*32, val_bits}
__device__ __half2 g_hh0[NN * 32];          // ego (fp16)
__device__ __half2 g_hh1[NN * 32];          // h1
__device__ __half2 g_hh2[NN * 32];          // h2

// ---- 1. init: g_cnt = 0, out = ego (fp32), hh0 = ego (fp16) ----
__global__ void k_init(const float4* __restrict__ eu,
                       const float4* __restrict__ ei,
                       float4* __restrict__ out) {
    int i = blockIdx.x * blockDim.x + threadIdx.x;
    if (i < NN) g_cnt[i] = 0;
    const int NU4 = NUM_USERS * EMBD / 4;
    const int NT4 = NN * EMBD / 4;
    if (i >= NT4) return;
    float4 v = (i < NU4) ? eu[i] : ei[i - NU4];
    out[i] = v;
    g_hh0[2 * i + 0] = __floats2half2_rn(v.x, v.y);
    g_hh0[2 * i + 1] = __floats2half2_rn(v.z, v.w);
}

// ---- 2. scatter COO -> fixed-capacity row buckets (8 elems/thread, MLP=8) ----
// pair = {col*32 (half2-index of node's row base), fp32 val bits}
__global__ void k_scatter(const int4* __restrict__ rows4,
                          const int4* __restrict__ cols4,
                          const float4* __restrict__ vals4) {
    int i = blockIdx.x * blockDim.x + threadIdx.x;
    if (i >= NNZ_C / 8) return;
    int4   r0 = rows4[2 * i], r1 = rows4[2 * i + 1];
    int4   c0 = cols4[2 * i], c1 = cols4[2 * i + 1];
    float4 v0 = vals4[2 * i], v1 = vals4[2 * i + 1];
    int p0 = atomicAdd(&g_cnt[r0.x], 1);
    int p1 = atomicAdd(&g_cnt[r0.y], 1);
    int p2 = atomicAdd(&g_cnt[r0.z], 1);
    int p3 = atomicAdd(&g_cnt[r0.w], 1);
    int p4 = atomicAdd(&g_cnt[r1.x], 1);
    int p5 = atomicAdd(&g_cnt[r1.y], 1);
    int p6 = atomicAdd(&g_cnt[r1.z], 1);
    int p7 = atomicAdd(&g_cnt[r1.w], 1);
    if (p0 < CAP) g_pair[r0.x * CAP + p0] = make_int2(c0.x * 32, __float_as_int(v0.x));
    if (p1 < CAP) g_pair[r0.y * CAP + p1] = make_int2(c0.y * 32, __float_as_int(v0.y));
    if (p2 < CAP) g_pair[r0.z * CAP + p2] = make_int2(c0.z * 32, __float_as_int(v0.z));
    if (p3 < CAP) g_pair[r0.w * CAP + p3] = make_int2(c0.w * 32, __float_as_int(v0.w));
    if (p4 < CAP) g_pair[r1.x * CAP + p4] = make_int2(c1.x * 32, __float_as_int(v1.x));
    if (p5 < CAP) g_pair[r1.y * CAP + p5] = make_int2(c1.y * 32, __float_as_int(v1.y));
    if (p6 < CAP) g_pair[r1.z * CAP + p6] = make_int2(c1.z * 32, __float_as_int(v1.z));
    if (p7 < CAP) g_pair[r1.w * CAP + p7] = make_int2(c1.w * 32, __float_as_int(v1.w));
}

// ---- 3-5. SpMM: warp-per-row, fp16 gather, fp32 accumulate (R10 shape) ----
// LAYER 0: hh0 -> hh1 ; LAYER 1: hh1 -> hh2 ;
// LAYER 2: gather hh2 -> regs, fused out = (ego + h1 + h2 + h3) * 0.25
template <int LAYER>
__global__ void __launch_bounds__(256, 8) k_spmm(float2* __restrict__ o2) {
    int w = (blockIdx.x * blockDim.x + threadIdx.x) >> 5;
    if (w >= NN) return;
    int lane = threadIdx.x & 31;

    const __half2* __restrict__ src =
        (LAYER == 0) ? g_hh0 : (LAYER == 1) ? g_hh1 : g_hh2;

    int beg = w * CAP;
    int deg = g_cnt[w];
    if (deg > CAP) deg = CAP;
    int end = beg + deg;

    float ax = 0.f, ay = 0.f;
    int j = beg;
    // 8-way straight-line unroll: 8 independent gathers in flight per warp
    for (; j + 8 <= end; j += 8) {
        int2 p[8];
        #pragma unroll
        for (int k = 0; k < 8; k++) p[k] = g_pair[j + k];
        __half2 x[8];
        #pragma unroll
        for (int k = 0; k < 8; k++) x[k] = src[p[k].x + lane];
        #pragma unroll
        for (int k = 0; k < 8; k++) {
            float2 f = __half22float2(x[k]);
            float  v = __int_as_float(p[k].y);
            ax += v * f.x;
            ay += v * f.y;
        }
    }
    for (; j < end; j++) {
        int2 p = g_pair[j];
        float2 f = __half22float2(src[p.x + lane]);
        float v = __int_as_float(p.y);
        ax += v * f.x; ay += v * f.y;
    }

    int oi = w * 32 + lane;
    if (LAYER == 0) {
        g_hh1[oi] = __floats2half2_rn(ax, ay);
    } else if (LAYER == 1) {
        g_hh2[oi] = __floats2half2_rn(ax, ay);
    } else {
        float2 o  = o2[oi];                       // ego (exact fp32)
        float2 h1 = __half22float2(g_hh1[oi]);
        float2 h2 = __half22float2(g_hh2[oi]);
        o.x = (o.x + h1.x + h2.x + ax) * 0.25f;
        o.y = (o.y + h1.y + h2.y + ay) * 0.25f;
        o2[oi] = o;
    }
}

extern "C" void kernel_launch(void* const* d_in, const int* in_sizes, int n_in,
                              void* d_out, int out_size) {
    const float* eu   = (const float*)d_in[0];   // emb_user  [100000*64]
    const float* ei   = (const float*)d_in[1];   // emb_item  [50000*64]
    const float* vals = (const float*)d_in[2];   // adj_vals  [NNZ]
    const int*   rows = (const int*)d_in[3];     // adj_rows  [NNZ]
    const int*   cols = (const int*)d_in[4];     // adj_cols  [NNZ]
    float* out = (float*)d_out;                  // [150000*64] f32

    // init (also zeroes cursors) must precede scatter
    k_init<<<(NN * EMBD / 4 + 255) / 256, 256>>>(
        (const float4*)eu, (const float4*)ei, (float4*)out);
    k_scatter<<<(NNZ_C / 8 + 255) / 256, 256>>>(
        (const int4*)rows, (const int4*)cols, (const float4*)vals);

    int sb = (NN * 32 + 255) / 256;  // warp per row
    k_spmm<0><<<sb, 256>>>((float2*)out);
    k_spmm<1><<<sb, 256>>>((float2*)out);
    k_spmm<2><<<sb, 256>>>((float2*)out);
}